// round 8
// baseline (speedup 1.0000x reference)
#include <cuda_runtime.h>
#include <cuda_bf16.h>
#include <cstdint>

// ============================================================================
// BatchConv2D 3x3, mma.sync bf16x3 (fp32 emulated), row-persistent CTAs.
// CTA = 256 thr (8 warps): (batch, x-half 128px, 8 rows), all 32 oc.
// 4 steps x 2 rows; warp = one row x 32px x 32oc (m32n32).
// Ring: 4 row-slots, (hi,lo) interleaved uint2 (stride 132 -> conflict-free
// LDS.64). Weights: per-lane uint4 quads {bh0,bh1,bl0,bl1} -> LDS.128.
// MMAs ordered in 3 rounds of 8 independent accumulators to hide HMMA latency.
// ============================================================================

#define BATCH 32
#define CH    32
#define HH    256
#define WW    256
#define HW    (HH * WW)

#define R_STR   132                 // uint2 per (slot,j) row; 132 % 16 == 4
#define SLOT_U2 (16 * R_STR)        // 2112 uint2 per row slot
#define NSLOT   4

#define SMEM_BIAS 0                                   // 128 B
#define SMEM_BQ   128                                 // 2304 uint4 = 36864 B
#define SMEM_RING (SMEM_BQ + 36864)                   // 36992
#define SMEM_TOTAL (SMEM_RING + NSLOT * SLOT_U2 * 8)  // 104576 B

__device__ __forceinline__ void mma_bf16(float* d, const uint32_t* a,
                                         uint32_t b0, uint32_t b1) {
    asm volatile(
        "mma.sync.aligned.m16n8k16.row.col.f32.bf16.bf16.f32 "
        "{%0,%1,%2,%3}, {%4,%5,%6,%7}, {%8,%9}, {%0,%1,%2,%3};\n"
        : "+f"(d[0]), "+f"(d[1]), "+f"(d[2]), "+f"(d[3])
        : "r"(a[0]), "r"(a[1]), "r"(a[2]), "r"(a[3]), "r"(b0), "r"(b1));
}

__device__ __forceinline__ uint32_t pack_hi(float v0, float v1,
                                            float& r0, float& r1) {
    __nv_bfloat16 h0 = __float2bfloat16(v0);
    __nv_bfloat16 h1 = __float2bfloat16(v1);
    r0 = v0 - __bfloat162float(h0);
    r1 = v1 - __bfloat162float(h1);
    return ((uint32_t)__bfloat16_as_ushort(h1) << 16) | __bfloat16_as_ushort(h0);
}

__device__ __forceinline__ uint32_t pack_lo(float r0, float r1) {
    __nv_bfloat16 l0 = __float2bfloat16(r0);
    __nv_bfloat16 l1 = __float2bfloat16(r1);
    return ((uint32_t)__bfloat16_as_ushort(l1) << 16) | __bfloat16_as_ushort(l0);
}

// Stage input row gy into ring slot (gy+4)&3. Zero-fills OOB. 256 threads.
__device__ __forceinline__ void stage_row(uint2* ring,
                                          const float* __restrict__ xb,
                                          int gy, int x0, int tid) {
    uint2* rs = ring + ((gy + 4) & 3) * SLOT_U2;
    const bool yok = (unsigned)gy < (unsigned)HH;
    const float* rowp = xb + (size_t)(yok ? gy : 0) * WW;
    for (int idx = tid; idx < 16 * 130; idx += 256) {
        const int j = idx / 130;
        const int i = idx - j * 130;
        const int gx = x0 - 1 + i;
        const bool ok = yok && ((unsigned)gx < (unsigned)WW);
        const float* px = rowp + (ok ? gx : 0);
        const float v0 = ok ? px[(2 * j) * HW] : 0.0f;
        const float v1 = ok ? px[(2 * j + 1) * HW] : 0.0f;
        float r0, r1;
        const uint32_t hi = pack_hi(v0, v1, r0, r1);
        const uint32_t lo = pack_lo(r0, r1);
        rs[j * R_STR + i] = make_uint2(hi, lo);
    }
}

__global__ void __launch_bounds__(256, 2)
batch_conv3x3_mma9_kernel(const float* __restrict__ x,
                          const float* __restrict__ w,
                          const float* __restrict__ bias,
                          float* __restrict__ out)
{
    extern __shared__ char smem[];
    float* bias_s = reinterpret_cast<float*>(smem + SMEM_BIAS);
    uint4* bq     = reinterpret_cast<uint4*>(smem + SMEM_BQ);
    uint2* ring   = reinterpret_cast<uint2*>(smem + SMEM_RING);

    const int tid  = threadIdx.x;       // 0..255
    const int lane = tid & 31;
    const int wid  = tid >> 5;          // 0..7
    const int xh   = blockIdx.x;        // 0..1
    const int yg   = blockIdx.y;        // 0..31
    const int b    = blockIdx.z;        // 0..31
    const int x0   = xh * 128;
    const int y0   = yg * 8;

    if (tid < CH) bias_s[tid] = bias[b * CH + tid];

    // ---- weights -> per-lane uint4 quads: bq[((tap*2+half)*4+nb)*32 + lane]
    //      lane = g*4+tg encodes oc = nb*8+g, k-pair kp = half*8+tg (and kp+4)
    const float* wg = w + (size_t)b * (CH * CH * 9);
    for (int idx = tid; idx < 18 * 4 * 32; idx += 256) {
        const int lq   = idx & 31;
        const int rest = idx >> 5;
        const int nb   = rest & 3;
        const int th   = rest >> 2;     // tap*2+half
        const int half = th & 1;
        const int tap  = th >> 1;
        const int oc   = nb * 8 + (lq >> 2);
        const int ci0  = 2 * (half * 8 + (lq & 3));
        const float v0 = wg[(oc * CH + ci0) * 9 + tap];
        const float v1 = wg[(oc * CH + ci0 + 1) * 9 + tap];
        const float v2 = wg[(oc * CH + ci0 + 8) * 9 + tap];
        const float v3 = wg[(oc * CH + ci0 + 9) * 9 + tap];
        float r0, r1, r2, r3;
        const uint32_t h0 = pack_hi(v0, v1, r0, r1);
        const uint32_t h1 = pack_hi(v2, v3, r2, r3);
        bq[idx] = make_uint4(h0, h1, pack_lo(r0, r1), pack_lo(r2, r3));
    }

    // ---- initial ring fill: input rows y0-1 .. y0+2
    const float* xb = x + (size_t)b * CH * HW;
    stage_row(ring, xb, y0 - 1, x0, tid);
    stage_row(ring, xb, y0,     x0, tid);
    stage_row(ring, xb, y0 + 1, x0, tid);
    stage_row(ring, xb, y0 + 2, x0, tid);
    __syncthreads();

    const int g    = lane >> 2;        // 0..7
    const int tg   = lane & 3;         // 0..3
    const int p0   = (wid & 3) * 32;   // pixel base within 128
    const int rsel = wid >> 2;         // 0/1: row within the pair

#pragma unroll 1
    for (int s = 0; s < 4; ++s) {
        const int row = y0 + 2 * s + rsel;

        float acc[2][4][4];
#pragma unroll
        for (int nb = 0; nb < 4; ++nb) {
            const float b0v = bias_s[nb * 8 + tg * 2];
            const float b1v = bias_s[nb * 8 + tg * 2 + 1];
#pragma unroll
            for (int t = 0; t < 2; ++t) {
                acc[t][nb][0] = b0v; acc[t][nb][1] = b1v;
                acc[t][nb][2] = b0v; acc[t][nb][3] = b1v;
            }
        }

#pragma unroll
        for (int tap = 0; tap < 9; ++tap) {
            const int dy = tap / 3, dx = tap % 3;
            const uint2* rs = ring + ((row - 1 + dy + 4) & 3) * SLOT_U2;
#pragma unroll
            for (int half = 0; half < 2; ++half) {
                // B quads: one LDS.128 per nb
                uint4 bqr[4];
#pragma unroll
                for (int nb = 0; nb < 4; ++nb)
                    bqr[nb] = bq[(((tap * 2 + half) * 4 + nb) << 5) + lane];

                // A fragments: 4 LDS.64 per t
                const int rj  = (half * 8 + tg) * R_STR;
                const int rj4 = rj + 4 * R_STR;
                uint32_t ah[2][4], al[2][4];
#pragma unroll
                for (int t = 0; t < 2; ++t) {
                    const int pb = p0 + t * 16 + g + dx;
                    const uint2 a0 = rs[rj + pb];
                    const uint2 a1 = rs[rj + pb + 8];
                    const uint2 a2 = rs[rj4 + pb];
                    const uint2 a3 = rs[rj4 + pb + 8];
                    ah[t][0] = a0.x; ah[t][1] = a1.x;
                    ah[t][2] = a2.x; ah[t][3] = a3.x;
                    al[t][0] = a0.y; al[t][1] = a1.y;
                    al[t][2] = a2.y; al[t][3] = a3.y;
                }

                // 24 MMAs in 3 rounds of 8 independent accumulators
#pragma unroll
                for (int nb = 0; nb < 4; ++nb) {
                    mma_bf16(acc[0][nb], ah[0], bqr[nb].x, bqr[nb].y);
                    mma_bf16(acc[1][nb], ah[1], bqr[nb].x, bqr[nb].y);
                }
#pragma unroll
                for (int nb = 0; nb < 4; ++nb) {
                    mma_bf16(acc[0][nb], al[0], bqr[nb].x, bqr[nb].y);
                    mma_bf16(acc[1][nb], al[1], bqr[nb].x, bqr[nb].y);
                }
#pragma unroll
                for (int nb = 0; nb < 4; ++nb) {
                    mma_bf16(acc[0][nb], ah[0], bqr[nb].z, bqr[nb].w);
                    mma_bf16(acc[1][nb], ah[1], bqr[nb].z, bqr[nb].w);
                }
            }
        }

        // ---- store this row's 32px x 32oc tile
        float* ob = out + (size_t)b * CH * HW + (size_t)row * WW + x0;
#pragma unroll
        for (int t = 0; t < 2; ++t) {
            const int p = p0 + t * 16 + g;
#pragma unroll
            for (int nb = 0; nb < 4; ++nb) {
                const int oc0 = nb * 8 + tg * 2;
                ob[(size_t)oc0 * HW + p]           = acc[t][nb][0];
                ob[(size_t)(oc0 + 1) * HW + p]     = acc[t][nb][1];
                ob[(size_t)oc0 * HW + p + 8]       = acc[t][nb][2];
                ob[(size_t)(oc0 + 1) * HW + p + 8] = acc[t][nb][3];
            }
        }

        // ---- ring advance
        __syncthreads();
        if (s < 3) {
            stage_row(ring, xb, y0 + 2 * s + 3, x0, tid);
            stage_row(ring, xb, y0 + 2 * s + 4, x0, tid);
            __syncthreads();
        }
    }
}

extern "C" void kernel_launch(void* const* d_in, const int* in_sizes, int n_in,
                              void* d_out, int out_size)
{
    const float* x    = (const float*)d_in[0];
    const float* w    = (const float*)d_in[1];
    const float* bias = (const float*)d_in[2];
    float* out        = (float*)d_out;

    cudaFuncSetAttribute(batch_conv3x3_mma9_kernel,
                         cudaFuncAttributeMaxDynamicSharedMemorySize,
                         SMEM_TOTAL);

    dim3 grid(2, HH / 8, BATCH);   // 2048 CTAs
    batch_conv3x3_mma9_kernel<<<grid, 256, SMEM_TOTAL>>>(x, w, bias, out);
}

// round 11
// speedup vs baseline: 1.2600x; 1.2600x over previous
#include <cuda_runtime.h>
#include <cuda_fp16.h>
#include <cstdint>

// ============================================================================
// BatchConv2D 3x3 via mma.sync f16 (2-term: x_fp16 * (wh + wl)), fp32 accum.
// CTA = 256 thr (8 warps): (batch, x-half 128px, 8 rows), all 32 oc.
// 4 steps x 2 rows; warp = one row x 32px x 32oc (m32n32). K = 288 per term.
// Ring: 4 row-slots of fp16x2 ci-pair words (stride 136 -> conflict-free LDS.32).
// Weights: (hi,lo) interleaved uint2, oc stride 148 -> conflict-free LDS.64.
// Error: only x-rounding (u=2^-11) -> aggregate rel_err ~3e-4 << 1e-3.
// ============================================================================

#define BATCH 32
#define CH    32
#define HH    256
#define WW    256
#define HW    (HH * WW)

#define A_STR   136                 // u32 per (slot,j) row; 136 % 32 == 8
#define SLOT_W  (16 * A_STR)        // 2176 u32 per row slot
#define WQ_STR  148                 // uint2 per oc; 148 % 16 == 4

#define SMEM_BIAS 0                                   // 128 B
#define SMEM_WQ   128                                 // 32*148*8 = 37888 B
#define SMEM_RING (SMEM_WQ + 37888)                   // 38016
#define SMEM_TOTAL (SMEM_RING + 4 * SLOT_W * 4)       // 72832 B

__device__ __forceinline__ void mma_f16(float* d, const uint32_t* a,
                                        uint32_t b0, uint32_t b1) {
    asm volatile(
        "mma.sync.aligned.m16n8k16.row.col.f32.f16.f16.f32 "
        "{%0,%1,%2,%3}, {%4,%5,%6,%7}, {%8,%9}, {%0,%1,%2,%3};\n"
        : "+f"(d[0]), "+f"(d[1]), "+f"(d[2]), "+f"(d[3])
        : "r"(a[0]), "r"(a[1]), "r"(a[2]), "r"(a[3]), "r"(b0), "r"(b1));
}

// Stage input row gy into ring slot (gy+4)&3 as packed fp16x2 ci-pairs.
__device__ __forceinline__ void stage_row(uint32_t* ring,
                                          const float* __restrict__ xb,
                                          int gy, int x0, int tid) {
    uint32_t* rs = ring + ((gy + 4) & 3) * SLOT_W;
    const bool yok = (unsigned)gy < (unsigned)HH;
    const float* rowp = xb + (size_t)(yok ? gy : 0) * WW;
    for (int idx = tid; idx < 16 * 130; idx += 256) {
        const int j = idx / 130;
        const int i = idx - j * 130;
        const int gx = x0 - 1 + i;
        const bool ok = yok && ((unsigned)gx < (unsigned)WW);
        const float* px = rowp + (ok ? gx : 0);
        const float v0 = ok ? px[(2 * j) * HW] : 0.0f;
        const float v1 = ok ? px[(2 * j + 1) * HW] : 0.0f;
        const __half2 h2 = __floats2half2_rn(v0, v1);
        rs[j * A_STR + i] = *reinterpret_cast<const uint32_t*>(&h2);
    }
}

__global__ void __launch_bounds__(256, 2)
batch_conv3x3_f16_kernel(const float* __restrict__ x,
                         const float* __restrict__ w,
                         const float* __restrict__ bias,
                         float* __restrict__ out)
{
    extern __shared__ char smem[];
    float*    bias_s = reinterpret_cast<float*>(smem + SMEM_BIAS);
    uint2*    wq     = reinterpret_cast<uint2*>(smem + SMEM_WQ);
    uint32_t* ring   = reinterpret_cast<uint32_t*>(smem + SMEM_RING);

    const int tid  = threadIdx.x;       // 0..255
    const int lane = tid & 31;
    const int wid  = tid >> 5;          // 0..7
    const int xh   = blockIdx.x;        // 0..1
    const int yg   = blockIdx.y;        // 0..31
    const int b    = blockIdx.z;        // 0..31
    const int x0   = xh * 128;
    const int y0   = yg * 8;

    if (tid < CH) bias_s[tid] = bias[b * CH + tid];

    // ---- weights -> SMEM: wq[oc*WQ_STR + tap*16 + kp] = (hi_pair, lo_pair)
    //      hi = fp16(w), lo = fp16(w - (float)hi)  (exact 2-term split)
    const float* wg = w + (size_t)b * (CH * CH * 9);
    for (int idx = tid; idx < CH * 9 * 16; idx += 256) {
        const int oc  = idx / 144;
        const int rem = idx - oc * 144;
        const int tap = rem >> 4;
        const int kp  = rem & 15;
        const float v0 = wg[(oc * CH + 2 * kp) * 9 + tap];
        const float v1 = wg[(oc * CH + 2 * kp + 1) * 9 + tap];
        const __half h0 = __float2half_rn(v0);
        const __half h1 = __float2half_rn(v1);
        const __half l0 = __float2half_rn(v0 - __half2float(h0));
        const __half l1 = __float2half_rn(v1 - __half2float(h1));
        const uint32_t hiw =
            ((uint32_t)__half_as_ushort(h1) << 16) | __half_as_ushort(h0);
        const uint32_t low =
            ((uint32_t)__half_as_ushort(l1) << 16) | __half_as_ushort(l0);
        wq[oc * WQ_STR + rem] = make_uint2(hiw, low);
    }

    // ---- initial ring fill: input rows y0-1 .. y0+2
    const float* xb = x + (size_t)b * CH * HW;
    stage_row(ring, xb, y0 - 1, x0, tid);
    stage_row(ring, xb, y0,     x0, tid);
    stage_row(ring, xb, y0 + 1, x0, tid);
    stage_row(ring, xb, y0 + 2, x0, tid);
    __syncthreads();

    const int g    = lane >> 2;        // 0..7
    const int tg   = lane & 3;         // 0..3
    const int p0   = (wid & 3) * 32;   // pixel base within 128
    const int rsel = wid >> 2;         // 0/1: row within the pair

#pragma unroll 1
    for (int s = 0; s < 4; ++s) {
        const int row = y0 + 2 * s + rsel;

        float acc[2][4][4];
#pragma unroll
        for (int nb = 0; nb < 4; ++nb) {
            const float b0v = bias_s[nb * 8 + tg * 2];
            const float b1v = bias_s[nb * 8 + tg * 2 + 1];
#pragma unroll
            for (int t = 0; t < 2; ++t) {
                acc[t][nb][0] = b0v; acc[t][nb][1] = b1v;
                acc[t][nb][2] = b0v; acc[t][nb][3] = b1v;
            }
        }

#pragma unroll
        for (int tap = 0; tap < 9; ++tap) {
            const int dy = tap / 3, dx = tap % 3;
            const uint32_t* rs = ring + ((row - 1 + dy + 4) & 3) * SLOT_W;
#pragma unroll
            for (int half = 0; half < 2; ++half) {
                // A fragments: 8 LDS.32
                const int rj  = (half * 8 + tg) * A_STR;
                const int rj4 = rj + 4 * A_STR;
                uint32_t a[2][4];
#pragma unroll
                for (int t = 0; t < 2; ++t) {
                    const int pb = p0 + t * 16 + g + dx;
                    a[t][0] = rs[rj + pb];   a[t][1] = rs[rj + pb + 8];
                    a[t][2] = rs[rj4 + pb];  a[t][3] = rs[rj4 + pb + 8];
                }
                // B fragments: 8 LDS.64 ((hi,lo) pairs for kp and kp+4)
                const int wbse = tap * 16 + half * 8 + tg;
                uint2 q0[4], q1[4];
#pragma unroll
                for (int nb = 0; nb < 4; ++nb) {
                    const int base = (nb * 8 + g) * WQ_STR + wbse;
                    q0[nb] = wq[base];
                    q1[nb] = wq[base + 4];
                }
                // 16 MMAs: 2 rounds over 8 independent accumulators
#pragma unroll
                for (int nb = 0; nb < 4; ++nb) {
                    mma_f16(acc[0][nb], a[0], q0[nb].x, q1[nb].x);
                    mma_f16(acc[1][nb], a[1], q0[nb].x, q1[nb].x);
                }
#pragma unroll
                for (int nb = 0; nb < 4; ++nb) {
                    mma_f16(acc[0][nb], a[0], q0[nb].y, q1[nb].y);
                    mma_f16(acc[1][nb], a[1], q0[nb].y, q1[nb].y);
                }
            }
        }

        // ---- store this row's 32px x 32oc tile
        float* ob = out + (size_t)b * CH * HW + (size_t)row * WW + x0;
#pragma unroll
        for (int t = 0; t < 2; ++t) {
            const int p = p0 + t * 16 + g;
#pragma unroll
            for (int nb = 0; nb < 4; ++nb) {
                const int oc0 = nb * 8 + tg * 2;
                ob[(size_t)oc0 * HW + p]           = acc[t][nb][0];
                ob[(size_t)(oc0 + 1) * HW + p]     = acc[t][nb][1];
                ob[(size_t)oc0 * HW + p + 8]       = acc[t][nb][2];
                ob[(size_t)(oc0 + 1) * HW + p + 8] = acc[t][nb][3];
            }
        }

        // ---- ring advance
        __syncthreads();
        if (s < 3) {
            stage_row(ring, xb, y0 + 2 * s + 3, x0, tid);
            stage_row(ring, xb, y0 + 2 * s + 4, x0, tid);
            __syncthreads();
        }
    }
}

extern "C" void kernel_launch(void* const* d_in, const int* in_sizes, int n_in,
                              void* d_out, int out_size)
{
    const float* x    = (const float*)d_in[0];
    const float* w    = (const float*)d_in[1];
    const float* bias = (const float*)d_in[2];
    float* out        = (float*)d_out;

    cudaFuncSetAttribute(batch_conv3x3_f16_kernel,
                         cudaFuncAttributeMaxDynamicSharedMemorySize,
                         SMEM_TOTAL);

    dim3 grid(2, HH / 8, BATCH);   // 2048 CTAs
    batch_conv3x3_f16_kernel<<<grid, 256, SMEM_TOTAL>>>(x, w, bias, out);
}